// round 3
// baseline (speedup 1.0000x reference)
#include <cuda_runtime.h>

#define BB 2048
#define SS 512
#define DD 128
#define HH 64
#define OO 8

typedef unsigned long long ull;

__device__ __forceinline__ void fma2(ull& d, ull a, ull b) {
    asm("fma.rn.f32x2 %0, %1, %2, %0;" : "+l"(d) : "l"(a), "l"(b));
}
__device__ __forceinline__ float fsum2(ull v) {
    float lo, hi;
    asm("mov.b64 {%0,%1}, %2;" : "=f"(lo), "=f"(hi) : "l"(v));
    return lo + hi;
}

// Scratch: xp[s][b][h] = x @ W_ih^T  (bias added in recurrence)
__device__ float g_xp[(long long)SS * BB * HH];
__device__ float g_z1[BB * 16];
__device__ float g_m1[HH], g_r1[HH];
__device__ float g_m2[16], g_r2[16];

// ---------------------------------------------------------------------------
// xp GEMM: [B*S, 128] x [128, 64] -> xp[s][b][j]. fp32 via packed f32x2.
// Tile: 128 m-rows x 64 j per block, K=128 single pass.
// Threads 256: thread tile 4 rows x 8 j. All LDS conflict-free/broadcast.
// ---------------------------------------------------------------------------
#define XTM 128
#define XSTR 132   // smem row stride (floats): 33*16B, conflict-free
__global__ __launch_bounds__(256) void xp_kernel(
    const float* __restrict__ x, const float* __restrict__ W_ih)
{
    extern __shared__ float smem[];
    float* xs = smem;               // [128][XSTR]
    float* ws = smem + XTM * XSTR;  // [64][XSTR]

    const int tid = threadIdx.x;
    const long long m0 = (long long)blockIdx.x * XTM;

    // stage W_ih [64][128]
    for (int i = tid; i < HH * 32; i += 256) {
        int j = i >> 5, c = i & 31;
        *(float4*)&ws[j * XSTR + c * 4] = *(const float4*)&W_ih[j * DD + c * 4];
    }
    // stage x tile [128][128]
    for (int i = tid; i < XTM * 32; i += 256) {
        int r = i >> 5, c = i & 31;
        *(float4*)&xs[r * XSTR + c * 4] = *(const float4*)&x[(m0 + r) * DD + c * 4];
    }
    __syncthreads();

    const int jg = tid & 7;        // 8 j-groups of 8 j
    const int rg = tid >> 3;       // 32 row-groups of 4 rows
    const float* xr0 = xs + (rg * 4 + 0) * XSTR;
    const float* xr1 = xs + (rg * 4 + 1) * XSTR;
    const float* xr2 = xs + (rg * 4 + 2) * XSTR;
    const float* xr3 = xs + (rg * 4 + 3) * XSTR;
    const float* wb  = ws + (jg * 8) * XSTR;

    ull acc[4][8];
    #pragma unroll
    for (int r = 0; r < 4; r++)
        #pragma unroll
        for (int j = 0; j < 8; j++) acc[r][j] = 0ull;

    #pragma unroll 4
    for (int q = 0; q < 32; q++) {
        ulonglong2 v0 = *(const ulonglong2*)(xr0 + q * 4);
        ulonglong2 v1 = *(const ulonglong2*)(xr1 + q * 4);
        ulonglong2 v2 = *(const ulonglong2*)(xr2 + q * 4);
        ulonglong2 v3 = *(const ulonglong2*)(xr3 + q * 4);
        #pragma unroll
        for (int j = 0; j < 8; j++) {
            ulonglong2 w = *(const ulonglong2*)(wb + j * XSTR + q * 4);
            fma2(acc[0][j], v0.x, w.x); fma2(acc[0][j], v0.y, w.y);
            fma2(acc[1][j], v1.x, w.x); fma2(acc[1][j], v1.y, w.y);
            fma2(acc[2][j], v2.x, w.x); fma2(acc[2][j], v2.y, w.y);
            fma2(acc[3][j], v3.x, w.x); fma2(acc[3][j], v3.y, w.y);
        }
    }

    #pragma unroll
    for (int r = 0; r < 4; r++) {
        long long m = m0 + rg * 4 + r;
        int b = (int)(m >> 9);       // m / S
        int s = (int)(m & 511);      // m % S
        float* o = g_xp + ((long long)s * BB + b) * HH + jg * 8;
        float4 f0 = make_float4(fsum2(acc[r][0]), fsum2(acc[r][1]),
                                fsum2(acc[r][2]), fsum2(acc[r][3]));
        float4 f1 = make_float4(fsum2(acc[r][4]), fsum2(acc[r][5]),
                                fsum2(acc[r][6]), fsum2(acc[r][7]));
        *(float4*)o = f0;
        *(float4*)(o + 4) = f1;
    }
}

// ---------------------------------------------------------------------------
// Recurrence: h = relu(xp[t] + bias + h @ W_hh^T), K=64.
// 128 blocks x 16 rows, 256 threads (8 warps). Warp owns 2 rows (warp-private:
// no __syncthreads in the loop). Lane owns 2 outputs; its 2 W_hh rows (128
// floats) live in REGISTERS. h LDS reads are pure broadcast (1 wavefront).
// ---------------------------------------------------------------------------
#define HSTR 68
__global__ __launch_bounds__(256) void rec_kernel(
    const float* __restrict__ h0, const float* __restrict__ W_hh,
    const float* __restrict__ b_ih, const float* __restrict__ b_hh,
    float* __restrict__ hT)
{
    __shared__ float hs[16 * HSTR];
    const int tid  = threadIdx.x;
    const int warp = tid >> 5, lane = tid & 31;
    const int r0 = warp * 2;             // local rows r0, r0+1
    const int j0 = lane * 2;             // outputs j0, j0+1
    const int brow0 = blockIdx.x * 16;

    // W_hh rows j0, j0+1 -> registers (packed pairs over k)
    ull wA[32], wB[32];
    const ull* pA = (const ull*)(W_hh + j0 * HH);
    const ull* pB = (const ull*)(W_hh + (j0 + 1) * HH);
    #pragma unroll
    for (int q = 0; q < 32; q++) { wA[q] = pA[q]; wB[q] = pB[q]; }

    // init h rows (warp-local)
    float2 i0 = *(const float2*)(h0 + (long long)(brow0 + r0) * HH + j0);
    float2 i1 = *(const float2*)(h0 + (long long)(brow0 + r0 + 1) * HH + j0);
    *(float2*)&hs[r0 * HSTR + j0] = i0;
    *(float2*)&hs[(r0 + 1) * HSTR + j0] = i1;

    const float bias0 = b_ih[j0] + b_hh[j0];
    const float bias1 = b_ih[j0 + 1] + b_hh[j0 + 1];

    const long long o0 = (long long)(brow0 + r0) * HH + j0;
    const long long o1 = o0 + HH;
    float2 xc0 = *(const float2*)(g_xp + o0);
    float2 xc1 = *(const float2*)(g_xp + o1);
    __syncwarp();

    const float* h0p = hs + r0 * HSTR;
    const float* h1p = hs + (r0 + 1) * HSTR;

    for (int t = 0; t < SS; ++t) {
        // prefetch next step's xp (consumed next iteration; full-step window)
        float2 xn0 = make_float2(0.f, 0.f), xn1 = xn0;
        if (t + 1 < SS) {
            const float* base = g_xp + (long long)(t + 1) * (BB * HH);
            xn0 = *(const float2*)(base + o0);
            xn1 = *(const float2*)(base + o1);
        }

        ull aA0 = 0, aB0 = 0, aA1 = 0, aB1 = 0;
        #pragma unroll
        for (int q = 0; q < 16; q++) {
            ulonglong2 v0 = *(const ulonglong2*)(h0p + q * 4);
            ulonglong2 v1 = *(const ulonglong2*)(h1p + q * 4);
            fma2(aA0, v0.x, wA[2 * q]); fma2(aA0, v0.y, wA[2 * q + 1]);
            fma2(aB0, v0.x, wB[2 * q]); fma2(aB0, v0.y, wB[2 * q + 1]);
            fma2(aA1, v1.x, wA[2 * q]); fma2(aA1, v1.y, wA[2 * q + 1]);
            fma2(aB1, v1.x, wB[2 * q]); fma2(aB1, v1.y, wB[2 * q + 1]);
        }
        float n00 = fmaxf(fsum2(aA0) + bias0 + xc0.x, 0.f);
        float n01 = fmaxf(fsum2(aB0) + bias1 + xc0.y, 0.f);
        float n10 = fmaxf(fsum2(aA1) + bias0 + xc1.x, 0.f);
        float n11 = fmaxf(fsum2(aB1) + bias1 + xc1.y, 0.f);
        __syncwarp();
        *(float2*)&hs[r0 * HSTR + j0] = make_float2(n00, n01);
        *(float2*)&hs[(r0 + 1) * HSTR + j0] = make_float2(n10, n11);
        __syncwarp();
        xc0 = xn0; xc1 = xn1;
    }

    *(float2*)&hT[(long long)(brow0 + r0) * HH + j0] =
        *(float2*)&hs[r0 * HSTR + j0];
    *(float2*)&hT[(long long)(brow0 + r0 + 1) * HH + j0] =
        *(float2*)&hs[(r0 + 1) * HSTR + j0];
}

// ---------------------------------------------------------------------------
// Head: BN1 -> fc1 -> relu -> BN2 -> fc2 (batch stats over B)
// ---------------------------------------------------------------------------
__global__ void stats1_kernel(const float* __restrict__ data) {
    int c = blockIdx.x;
    float s = 0.f, s2 = 0.f;
    for (int r = threadIdx.x; r < BB; r += blockDim.x) {
        float v = data[r * HH + c];
        s += v; s2 += v * v;
    }
    __shared__ float sh[256], sh2[256];
    sh[threadIdx.x] = s; sh2[threadIdx.x] = s2;
    __syncthreads();
    for (int st = 128; st > 0; st >>= 1) {
        if (threadIdx.x < st) {
            sh[threadIdx.x]  += sh[threadIdx.x + st];
            sh2[threadIdx.x] += sh2[threadIdx.x + st];
        }
        __syncthreads();
    }
    if (threadIdx.x == 0) {
        float m = sh[0] / BB;
        float var = sh2[0] / BB - m * m;
        g_m1[c] = m;
        g_r1[c] = rsqrtf(var + 1e-5f);
    }
}

__global__ void fc1_kernel(const float* __restrict__ h,
                           const float* __restrict__ g1, const float* __restrict__ be1,
                           const float* __restrict__ W, const float* __restrict__ wb) {
    __shared__ float sc[HH], sf[HH];
    if (threadIdx.x < HH) {
        float a = g_r1[threadIdx.x] * g1[threadIdx.x];
        sc[threadIdx.x] = a;
        sf[threadIdx.x] = be1[threadIdx.x] - g_m1[threadIdx.x] * a;
    }
    __syncthreads();
    int idx = blockIdx.x * blockDim.x + threadIdx.x;
    int b = idx >> 4, c = idx & 15;
    float acc = wb[c];
    #pragma unroll
    for (int k = 0; k < HH; k++)
        acc += (h[b * HH + k] * sc[k] + sf[k]) * W[c * HH + k];
    g_z1[idx] = fmaxf(acc, 0.f);
}

__global__ void stats2_kernel() {
    int c = blockIdx.x;
    float s = 0.f, s2 = 0.f;
    for (int r = threadIdx.x; r < BB; r += blockDim.x) {
        float v = g_z1[r * 16 + c];
        s += v; s2 += v * v;
    }
    __shared__ float sh[256], sh2[256];
    sh[threadIdx.x] = s; sh2[threadIdx.x] = s2;
    __syncthreads();
    for (int st = 128; st > 0; st >>= 1) {
        if (threadIdx.x < st) {
            sh[threadIdx.x]  += sh[threadIdx.x + st];
            sh2[threadIdx.x] += sh2[threadIdx.x + st];
        }
        __syncthreads();
    }
    if (threadIdx.x == 0) {
        float m = sh[0] / BB;
        float var = sh2[0] / BB - m * m;
        g_m2[c] = m;
        g_r2[c] = rsqrtf(var + 1e-5f);
    }
}

__global__ void fc2_kernel(const float* __restrict__ g2, const float* __restrict__ be2,
                           const float* __restrict__ W, const float* __restrict__ wb,
                           float* __restrict__ out) {
    __shared__ float sc[16], sf[16];
    if (threadIdx.x < 16) {
        float a = g_r2[threadIdx.x] * g2[threadIdx.x];
        sc[threadIdx.x] = a;
        sf[threadIdx.x] = be2[threadIdx.x] - g_m2[threadIdx.x] * a;
    }
    __syncthreads();
    int idx = blockIdx.x * blockDim.x + threadIdx.x;
    int b = idx >> 3, c = idx & 7;
    float acc = wb[c];
    #pragma unroll
    for (int k = 0; k < 16; k++)
        acc += (g_z1[b * 16 + k] * sc[k] + sf[k]) * W[c * 16 + k];
    out[idx] = acc;
}

// ---------------------------------------------------------------------------
extern "C" void kernel_launch(void* const* d_in, const int* in_sizes, int n_in,
                              void* d_out, int out_size) {
    const float* x    = (const float*)d_in[0];
    const float* h0   = (const float*)d_in[1];
    const float* W_ih = (const float*)d_in[2];
    const float* W_hh = (const float*)d_in[3];
    const float* b_ih = (const float*)d_in[4];
    const float* b_hh = (const float*)d_in[5];
    const float* bn1g = (const float*)d_in[6];
    const float* bn1b = (const float*)d_in[7];
    const float* fc1W = (const float*)d_in[8];
    const float* fc1b = (const float*)d_in[9];
    const float* bn2g = (const float*)d_in[10];
    const float* bn2b = (const float*)d_in[11];
    const float* fc2W = (const float*)d_in[12];
    const float* fc2b = (const float*)d_in[13];

    float* out = (float*)d_out;          // [2048, 8]
    float* hT  = out + BB * OO;          // [1, 2048, 64]

    size_t xp_smem = (size_t)(XTM + HH) * XSTR * sizeof(float);  // ~101 KB
    static int configured = 0;
    cudaFuncSetAttribute(xp_kernel, cudaFuncAttributeMaxDynamicSharedMemorySize,
                         (int)xp_smem);
    (void)configured;

    xp_kernel<<<(BB * SS) / XTM, 256, xp_smem>>>(x, W_ih);
    rec_kernel<<<BB / 16, 256>>>(h0, W_hh, b_ih, b_hh, hT);
    stats1_kernel<<<HH, 256>>>(hT);
    fc1_kernel<<<(BB * 16) / 256, 256>>>(hT, bn1g, bn1b, fc1W, fc1b);
    stats2_kernel<<<16, 256>>>();
    fc2_kernel<<<(BB * 8) / 256, 256>>>(bn2g, bn2b, fc2W, fc2b, out);
}

// round 4
// speedup vs baseline: 1.2993x; 1.2993x over previous
#include <cuda_runtime.h>

#define BB 2048
#define SS 512
#define DD 128
#define HH 64
#define OO 8

typedef unsigned long long ull;

__device__ __forceinline__ void fma2(ull& d, ull a, ull b) {
    asm("fma.rn.f32x2 %0, %1, %2, %0;" : "+l"(d) : "l"(a), "l"(b));
}
__device__ __forceinline__ float fsum2(ull v) {
    float lo, hi;
    asm("mov.b64 {%0,%1}, %2;" : "=f"(lo), "=f"(hi) : "l"(v));
    return lo + hi;
}

// xp[m][h] = (x @ W_ih^T)[m][h],  m = b*S + s  (row-major, matches rec access)
__device__ float g_xp[(long long)BB * SS * HH];
__device__ float g_z1[BB * 16];
__device__ float g_m1[HH], g_r1[HH];
__device__ float g_m2[16], g_r2[16];

// ---------------------------------------------------------------------------
// xp GEMM v2: [B*S,128] @ [128,64]^T.
// Block = 128 threads (4 warps) x 64 rows. Warp owns 16 rows.
// Lane owns j-pair (j0 = lane*2); W_ih rows j0,j0+1 live in REGISTERS,
// K split into 2 chunks of 64 so w regs = 64 ull (128 regs, no spill).
// x is read via pure-broadcast LDS.128 (1 wavefront each): per (row,chunk)
// 16 broadcast wf vs 64 fma2 (128 issue cyc) -> FMA-bound, crossbar ~50%.
// ---------------------------------------------------------------------------
#define XROWS 64
#define XSTR 132   // floats; row offset 528 B -> 16B aligned, conflict-irrelevant (broadcast)
__global__ __launch_bounds__(128) void xp_kernel(
    const float* __restrict__ x, const float* __restrict__ W_ih)
{
    __shared__ float xs[XROWS * XSTR];
    const int tid = threadIdx.x;
    const int warp = tid >> 5, lane = tid & 31;
    const int j0 = lane * 2;
    const long long m0 = (long long)blockIdx.x * XROWS;

    // stage x tile [64][128] coalesced
    for (int i = tid; i < XROWS * 32; i += 128) {
        int r = i >> 5, c = i & 31;
        *(float4*)&xs[r * XSTR + c * 4] = *(const float4*)&x[(m0 + r) * DD + c * 4];
    }
    __syncthreads();

    float2 acc[16];
    #pragma unroll
    for (int r = 0; r < 16; r++) acc[r] = make_float2(0.f, 0.f);

    #pragma unroll
    for (int kc = 0; kc < 2; kc++) {
        // W rows j0, j0+1, chunk [kc*64, kc*64+64) -> registers
        ull wA[32], wB[32];
        const ull* pA = (const ull*)(W_ih + j0 * DD + kc * 64);
        const ull* pB = (const ull*)(W_ih + (j0 + 1) * DD + kc * 64);
        #pragma unroll
        for (int i = 0; i < 32; i++) { wA[i] = pA[i]; wB[i] = pB[i]; }

        #pragma unroll 2
        for (int r = 0; r < 16; r++) {
            const float* xr = xs + (warp * 16 + r) * XSTR + kc * 64;
            ull a0 = 0, a1 = 0, b0 = 0, b1 = 0;   // 4 chains: hide fma latency
            #pragma unroll
            for (int q = 0; q < 16; q++) {
                ulonglong2 v = *(const ulonglong2*)(xr + q * 4);  // broadcast
                fma2(a0, v.x, wA[2 * q]); fma2(a1, v.y, wA[2 * q + 1]);
                fma2(b0, v.x, wB[2 * q]); fma2(b1, v.y, wB[2 * q + 1]);
            }
            acc[r].x += fsum2(a0) + fsum2(a1);
            acc[r].y += fsum2(b0) + fsum2(b1);
        }
    }

    #pragma unroll
    for (int r = 0; r < 16; r++) {
        long long m = m0 + warp * 16 + r;
        *(float2*)&g_xp[m * HH + j0] = acc[r];   // coalesced 256B per warp
    }
}

// ---------------------------------------------------------------------------
// Recurrence v2: h = relu(xp[t] + bias + h @ W_hh^T), K=64.
// 256 blocks x 256 threads; warp owns ONE batch row for all 512 steps.
// Lane owns j-pair with its 2 W_hh rows in REGISTERS (64 ull). h broadcast
// from a warp-private smem row (16 LDS.128 wf/step). xp prefetched 2 steps
// ahead to cover DRAM latency. No __syncthreads in the loop.
// ---------------------------------------------------------------------------
#define RBR 8      // rows (warps) per block
#define HSTR 68    // smem row stride (272 B, 16B-aligned)
__global__ __launch_bounds__(RBR * 32) void rec_kernel(
    const float* __restrict__ h0, const float* __restrict__ W_hh,
    const float* __restrict__ b_ih, const float* __restrict__ b_hh,
    float* __restrict__ hT)
{
    __shared__ float hs[RBR * HSTR];
    const int tid = threadIdx.x;
    const int warp = tid >> 5, lane = tid & 31;
    const int j0 = lane * 2;
    const int row = blockIdx.x * RBR + warp;     // global batch row

    ull wA[32], wB[32];
    const ull* pA = (const ull*)(W_hh + j0 * HH);
    const ull* pB = (const ull*)(W_hh + (j0 + 1) * HH);
    #pragma unroll
    for (int i = 0; i < 32; i++) { wA[i] = pA[i]; wB[i] = pB[i]; }

    float* hrow = hs + warp * HSTR;
    *(float2*)&hrow[j0] = *(const float2*)(h0 + (long long)row * HH + j0);

    const float bias0 = b_ih[j0] + b_hh[j0];
    const float bias1 = b_ih[j0 + 1] + b_hh[j0 + 1];

    const float* xrow = g_xp + (long long)row * SS * HH + j0;  // [t][..] stride HH
    float2 xc  = *(const float2*)(xrow);             // t
    float2 xn  = *(const float2*)(xrow + HH);        // t+1
    __syncwarp();

    for (int t = 0; t < SS; ++t) {
        // prefetch t+2
        float2 xnn = make_float2(0.f, 0.f);
        if (t + 2 < SS) xnn = *(const float2*)(xrow + (long long)(t + 2) * HH);

        ull a0 = 0, a1 = 0, b0 = 0, b1 = 0;
        #pragma unroll
        for (int q = 0; q < 16; q++) {
            ulonglong2 v = *(const ulonglong2*)(hrow + q * 4);   // broadcast
            fma2(a0, v.x, wA[2 * q]); fma2(a1, v.y, wA[2 * q + 1]);
            fma2(b0, v.x, wB[2 * q]); fma2(b1, v.y, wB[2 * q + 1]);
        }
        float n0 = fmaxf(fsum2(a0) + fsum2(a1) + bias0 + xc.x, 0.f);
        float n1 = fmaxf(fsum2(b0) + fsum2(b1) + bias1 + xc.y, 0.f);
        __syncwarp();
        *(float2*)&hrow[j0] = make_float2(n0, n1);
        __syncwarp();
        xc = xn; xn = xnn;
    }

    *(float2*)&hT[(long long)row * HH + j0] = *(float2*)&hrow[j0];
}

// ---------------------------------------------------------------------------
// Head: BN1 -> fc1 -> relu -> BN2 -> fc2 (batch stats over B)
// ---------------------------------------------------------------------------
__global__ void stats1_kernel(const float* __restrict__ data) {
    int c = blockIdx.x;
    float s = 0.f, s2 = 0.f;
    for (int r = threadIdx.x; r < BB; r += blockDim.x) {
        float v = data[r * HH + c];
        s += v; s2 += v * v;
    }
    __shared__ float sh[256], sh2[256];
    sh[threadIdx.x] = s; sh2[threadIdx.x] = s2;
    __syncthreads();
    for (int st = 128; st > 0; st >>= 1) {
        if (threadIdx.x < st) {
            sh[threadIdx.x]  += sh[threadIdx.x + st];
            sh2[threadIdx.x] += sh2[threadIdx.x + st];
        }
        __syncthreads();
    }
    if (threadIdx.x == 0) {
        float m = sh[0] / BB;
        float var = sh2[0] / BB - m * m;
        g_m1[c] = m;
        g_r1[c] = rsqrtf(var + 1e-5f);
    }
}

__global__ void fc1_kernel(const float* __restrict__ h,
                           const float* __restrict__ g1, const float* __restrict__ be1,
                           const float* __restrict__ W, const float* __restrict__ wb) {
    __shared__ float sc[HH], sf[HH];
    if (threadIdx.x < HH) {
        float a = g_r1[threadIdx.x] * g1[threadIdx.x];
        sc[threadIdx.x] = a;
        sf[threadIdx.x] = be1[threadIdx.x] - g_m1[threadIdx.x] * a;
    }
    __syncthreads();
    int idx = blockIdx.x * blockDim.x + threadIdx.x;
    int b = idx >> 4, c = idx & 15;
    float acc = wb[c];
    #pragma unroll
    for (int k = 0; k < HH; k++)
        acc += (h[b * HH + k] * sc[k] + sf[k]) * W[c * HH + k];
    g_z1[idx] = fmaxf(acc, 0.f);
}

__global__ void stats2_kernel() {
    int c = blockIdx.x;
    float s = 0.f, s2 = 0.f;
    for (int r = threadIdx.x; r < BB; r += blockDim.x) {
        float v = g_z1[r * 16 + c];
        s += v; s2 += v * v;
    }
    __shared__ float sh[256], sh2[256];
    sh[threadIdx.x] = s; sh2[threadIdx.x] = s2;
    __syncthreads();
    for (int st = 128; st > 0; st >>= 1) {
        if (threadIdx.x < st) {
            sh[threadIdx.x]  += sh[threadIdx.x + st];
            sh2[threadIdx.x] += sh2[threadIdx.x + st];
        }
        __syncthreads();
    }
    if (threadIdx.x == 0) {
        float m = sh[0] / BB;
        float var = sh2[0] / BB - m * m;
        g_m2[c] = m;
        g_r2[c] = rsqrtf(var + 1e-5f);
    }
}

__global__ void fc2_kernel(const float* __restrict__ g2, const float* __restrict__ be2,
                           const float* __restrict__ W, const float* __restrict__ wb,
                           float* __restrict__ out) {
    __shared__ float sc[16], sf[16];
    if (threadIdx.x < 16) {
        float a = g_r2[threadIdx.x] * g2[threadIdx.x];
        sc[threadIdx.x] = a;
        sf[threadIdx.x] = be2[threadIdx.x] - g_m2[threadIdx.x] * a;
    }
    __syncthreads();
    int idx = blockIdx.x * blockDim.x + threadIdx.x;
    int b = idx >> 3, c = idx & 7;
    float acc = wb[c];
    #pragma unroll
    for (int k = 0; k < 16; k++)
        acc += (g_z1[b * 16 + k] * sc[k] + sf[k]) * W[c * 16 + k];
    out[idx] = acc;
}

// ---------------------------------------------------------------------------
extern "C" void kernel_launch(void* const* d_in, const int* in_sizes, int n_in,
                              void* d_out, int out_size) {
    const float* x    = (const float*)d_in[0];
    const float* h0   = (const float*)d_in[1];
    const float* W_ih = (const float*)d_in[2];
    const float* W_hh = (const float*)d_in[3];
    const float* b_ih = (const float*)d_in[4];
    const float* b_hh = (const float*)d_in[5];
    const float* bn1g = (const float*)d_in[6];
    const float* bn1b = (const float*)d_in[7];
    const float* fc1W = (const float*)d_in[8];
    const float* fc1b = (const float*)d_in[9];
    const float* bn2g = (const float*)d_in[10];
    const float* bn2b = (const float*)d_in[11];
    const float* fc2W = (const float*)d_in[12];
    const float* fc2b = (const float*)d_in[13];

    float* out = (float*)d_out;          // [2048, 8]
    float* hT  = out + BB * OO;          // [1, 2048, 64]

    xp_kernel<<<(BB * SS) / XROWS, 128>>>(x, W_ih);
    rec_kernel<<<BB / RBR, RBR * 32>>>(h0, W_hh, b_ih, b_hh, hT);
    stats1_kernel<<<HH, 256>>>(hT);
    fc1_kernel<<<(BB * 16) / 256, 256>>>(hT, bn1g, bn1b, fc1W, fc1b);
    stats2_kernel<<<16, 256>>>();
    fc2_kernel<<<(BB * 8) / 256, 256>>>(bn2g, bn2b, fc2W, fc2b, out);
}

// round 5
// speedup vs baseline: 2.5436x; 1.9577x over previous
#include <cuda_runtime.h>

#define BB 2048
#define SS 512
#define DD 128
#define HH 64
#define OO 8

typedef unsigned long long ull;

__device__ __forceinline__ void fma2(ull& d, ull a, ull b) {
    asm("fma.rn.f32x2 %0, %1, %2, %0;" : "+l"(d) : "l"(a), "l"(b));
}
__device__ __forceinline__ float fsum2(ull v) {
    float lo, hi;
    asm("mov.b64 {%0,%1}, %2;" : "=f"(lo), "=f"(hi) : "l"(v));
    return lo + hi;
}

// xp[m][h] = (x @ W_ih^T)[m][h],  m = b*S + s
__device__ float g_xp[(long long)BB * SS * HH];
// W_ih packed lane-interleaved for coalesced register fill:
// g_wpA[kc][i][l] = (W_ih[2l][kc*64+2i], W_ih[2l][kc*64+2i+1]), g_wpB row 2l+1
__device__ ull g_wpA[2][32][32];
__device__ ull g_wpB[2][32][32];
__device__ float g_z1[BB * 16];
__device__ float g_m1[HH], g_r1[HH];
__device__ float g_m2[16], g_r2[16];

// ---------------------------------------------------------------------------
__global__ void dummy_kernel() {}

__global__ void prep_kernel(const float* __restrict__ W_ih) {
    // 2*32*32 = 2048 entries per array
    for (int e = threadIdx.x; e < 2048; e += blockDim.x) {
        int kc = e >> 10, i = (e >> 5) & 31, l = e & 31;
        int k = kc * 64 + 2 * i;
        float a0 = W_ih[(2 * l) * DD + k];
        float a1 = W_ih[(2 * l) * DD + k + 1];
        float b0 = W_ih[(2 * l + 1) * DD + k];
        float b1 = W_ih[(2 * l + 1) * DD + k + 1];
        ull pa, pb;
        asm("mov.b64 %0, {%1,%2};" : "=l"(pa) : "f"(a0), "f"(a1));
        asm("mov.b64 %0, {%1,%2};" : "=l"(pb) : "f"(b0), "f"(b1));
        g_wpA[kc][i][l] = pa;
        g_wpB[kc][i][l] = pb;
    }
}

// ---------------------------------------------------------------------------
// xp GEMM v3: [B*S,128] @ [128,64]^T.
// Block = 128 threads (4 warps), 64 m-rows. Warp owns 16 rows; lane owns
// j-pair with W in REGISTERS, filled via COALESCED LDG.64 from the packed
// copy (2 wavefronts per load instead of 32). x broadcast from smem.
// Output stores are contiguous 256 B per warp. FMA-issue bound.
// ---------------------------------------------------------------------------
#define XROWS 64
#define XSTR 132
__global__ __launch_bounds__(128) void xp_kernel(
    const float* __restrict__ x)
{
    __shared__ float xs[XROWS * XSTR];
    const int tid = threadIdx.x;
    const int warp = tid >> 5, lane = tid & 31;
    const int j0 = lane * 2;
    const long long m0 = (long long)blockIdx.x * XROWS;

    // stage x tile [64][128] coalesced
    for (int i = tid; i < XROWS * 32; i += 128) {
        int r = i >> 5, c = i & 31;
        *(float4*)&xs[r * XSTR + c * 4] = *(const float4*)&x[(m0 + r) * DD + c * 4];
    }
    __syncthreads();

    float2 acc[16];
    #pragma unroll
    for (int r = 0; r < 16; r++) acc[r] = make_float2(0.f, 0.f);

    #pragma unroll
    for (int kc = 0; kc < 2; kc++) {
        // coalesced register fill: lane-interleaved packed W
        ull wA[32], wB[32];
        #pragma unroll
        for (int i = 0; i < 32; i++) { wA[i] = g_wpA[kc][i][lane]; wB[i] = g_wpB[kc][i][lane]; }

        #pragma unroll 2
        for (int r = 0; r < 16; r++) {
            const float* xr = xs + (warp * 16 + r) * XSTR + kc * 64;
            ull a0 = 0, a1 = 0, b0 = 0, b1 = 0;
            #pragma unroll
            for (int q = 0; q < 16; q++) {
                ulonglong2 v = *(const ulonglong2*)(xr + q * 4);  // broadcast
                fma2(a0, v.x, wA[2 * q]); fma2(a1, v.y, wA[2 * q + 1]);
                fma2(b0, v.x, wB[2 * q]); fma2(b1, v.y, wB[2 * q + 1]);
            }
            acc[r].x += fsum2(a0) + fsum2(a1);
            acc[r].y += fsum2(b0) + fsum2(b1);
        }
    }

    #pragma unroll
    for (int r = 0; r < 16; r++) {
        long long m = m0 + warp * 16 + r;
        *(float2*)&g_xp[m * HH + j0] = acc[r];   // contiguous 256B per warp
    }
}

// ---------------------------------------------------------------------------
// Recurrence: h = relu(xp[t] + bias + h @ W_hh^T), K=64.
// Warp owns one batch row; lane owns j-pair, W_hh in registers; h broadcast
// from warp-private smem row; xp reads coalesced (256B/warp/step).
// ---------------------------------------------------------------------------
#define RBR 8
#define HSTR 68
__global__ __launch_bounds__(RBR * 32) void rec_kernel(
    const float* __restrict__ h0, const float* __restrict__ W_hh,
    const float* __restrict__ b_ih, const float* __restrict__ b_hh,
    float* __restrict__ hT)
{
    __shared__ float hs[RBR * HSTR];
    const int tid = threadIdx.x;
    const int warp = tid >> 5, lane = tid & 31;
    const int j0 = lane * 2;
    const int row = blockIdx.x * RBR + warp;

    ull wA[32], wB[32];
    const ull* pA = (const ull*)(W_hh + j0 * HH);
    const ull* pB = (const ull*)(W_hh + (j0 + 1) * HH);
    #pragma unroll
    for (int i = 0; i < 32; i++) { wA[i] = pA[i]; wB[i] = pB[i]; }

    float* hrow = hs + warp * HSTR;
    *(float2*)&hrow[j0] = *(const float2*)(h0 + (long long)row * HH + j0);

    const float bias0 = b_ih[j0] + b_hh[j0];
    const float bias1 = b_ih[j0 + 1] + b_hh[j0 + 1];

    const float* xrow = g_xp + (long long)row * SS * HH + j0;
    float2 xc = *(const float2*)(xrow);
    float2 xn = *(const float2*)(xrow + HH);
    __syncwarp();

    for (int t = 0; t < SS; ++t) {
        float2 xnn = make_float2(0.f, 0.f);
        if (t + 2 < SS) xnn = *(const float2*)(xrow + (long long)(t + 2) * HH);

        ull a0 = 0, a1 = 0, b0 = 0, b1 = 0;
        #pragma unroll
        for (int q = 0; q < 16; q++) {
            ulonglong2 v = *(const ulonglong2*)(hrow + q * 4);   // broadcast
            fma2(a0, v.x, wA[2 * q]); fma2(a1, v.y, wA[2 * q + 1]);
            fma2(b0, v.x, wB[2 * q]); fma2(b1, v.y, wB[2 * q + 1]);
        }
        float n0 = fmaxf(fsum2(a0) + fsum2(a1) + bias0 + xc.x, 0.f);
        float n1 = fmaxf(fsum2(b0) + fsum2(b1) + bias1 + xc.y, 0.f);
        __syncwarp();
        *(float2*)&hrow[j0] = make_float2(n0, n1);
        __syncwarp();
        xc = xn; xn = xnn;
    }

    *(float2*)&hT[(long long)row * HH + j0] = *(float2*)&hrow[j0];
}

// ---------------------------------------------------------------------------
// Head kernels
// ---------------------------------------------------------------------------
__global__ void stats1_kernel(const float* __restrict__ data) {
    int c = blockIdx.x;
    float s = 0.f, s2 = 0.f;
    for (int r = threadIdx.x; r < BB; r += blockDim.x) {
        float v = data[r * HH + c];
        s += v; s2 += v * v;
    }
    __shared__ float sh[256], sh2[256];
    sh[threadIdx.x] = s; sh2[threadIdx.x] = s2;
    __syncthreads();
    for (int st = 128; st > 0; st >>= 1) {
        if (threadIdx.x < st) {
            sh[threadIdx.x]  += sh[threadIdx.x + st];
            sh2[threadIdx.x] += sh2[threadIdx.x + st];
        }
        __syncthreads();
    }
    if (threadIdx.x == 0) {
        float m = sh[0] / BB;
        float var = sh2[0] / BB - m * m;
        g_m1[c] = m;
        g_r1[c] = rsqrtf(var + 1e-5f);
    }
}

__global__ void fc1_kernel(const float* __restrict__ h,
                           const float* __restrict__ g1, const float* __restrict__ be1,
                           const float* __restrict__ W, const float* __restrict__ wb) {
    __shared__ float sc[HH], sf[HH];
    if (threadIdx.x < HH) {
        float a = g_r1[threadIdx.x] * g1[threadIdx.x];
        sc[threadIdx.x] = a;
        sf[threadIdx.x] = be1[threadIdx.x] - g_m1[threadIdx.x] * a;
    }
    __syncthreads();
    int idx = blockIdx.x * blockDim.x + threadIdx.x;
    int b = idx >> 4, c = idx & 15;
    float acc = wb[c];
    #pragma unroll
    for (int k = 0; k < HH; k++)
        acc += (h[b * HH + k] * sc[k] + sf[k]) * W[c * HH + k];
    g_z1[idx] = fmaxf(acc, 0.f);
}

__global__ void stats2_kernel() {
    int c = blockIdx.x;
    float s = 0.f, s2 = 0.f;
    for (int r = threadIdx.x; r < BB; r += blockDim.x) {
        float v = g_z1[r * 16 + c];
        s += v; s2 += v * v;
    }
    __shared__ float sh[256], sh2[256];
    sh[threadIdx.x] = s; sh2[threadIdx.x] = s2;
    __syncthreads();
    for (int st = 128; st > 0; st >>= 1) {
        if (threadIdx.x < st) {
            sh[threadIdx.x]  += sh[threadIdx.x + st];
            sh2[threadIdx.x] += sh2[threadIdx.x + st];
        }
        __syncthreads();
    }
    if (threadIdx.x == 0) {
        float m = sh[0] / BB;
        float var = sh2[0] / BB - m * m;
        g_m2[c] = m;
        g_r2[c] = rsqrtf(var + 1e-5f);
    }
}

__global__ void fc2_kernel(const float* __restrict__ g2, const float* __restrict__ be2,
                           const float* __restrict__ W, const float* __restrict__ wb,
                           float* __restrict__ out) {
    __shared__ float sc[16], sf[16];
    if (threadIdx.x < 16) {
        float a = g_r2[threadIdx.x] * g2[threadIdx.x];
        sc[threadIdx.x] = a;
        sf[threadIdx.x] = be2[threadIdx.x] - g_m2[threadIdx.x] * a;
    }
    __syncthreads();
    int idx = blockIdx.x * blockDim.x + threadIdx.x;
    int b = idx >> 3, c = idx & 7;
    float acc = wb[c];
    #pragma unroll
    for (int k = 0; k < 16; k++)
        acc += (g_z1[b * 16 + k] * sc[k] + sf[k]) * W[c * 16 + k];
    out[idx] = acc;
}

// ---------------------------------------------------------------------------
extern "C" void kernel_launch(void* const* d_in, const int* in_sizes, int n_in,
                              void* d_out, int out_size) {
    const float* x    = (const float*)d_in[0];
    const float* h0   = (const float*)d_in[1];
    const float* W_ih = (const float*)d_in[2];
    const float* W_hh = (const float*)d_in[3];
    const float* b_ih = (const float*)d_in[4];
    const float* b_hh = (const float*)d_in[5];
    const float* bn1g = (const float*)d_in[6];
    const float* bn1b = (const float*)d_in[7];
    const float* fc1W = (const float*)d_in[8];
    const float* fc1b = (const float*)d_in[9];
    const float* bn2g = (const float*)d_in[10];
    const float* bn2b = (const float*)d_in[11];
    const float* fc2W = (const float*)d_in[12];
    const float* fc2b = (const float*)d_in[13];

    float* out = (float*)d_out;          // [2048, 8]
    float* hT  = out + BB * OO;          // [1, 2048, 64]

    // launches #1-#3: dummies + prep so xp_kernel is launch #4 (the slot the
    // profiler has been capturing) — observability for the dominant kernel.
    dummy_kernel<<<1, 32>>>();
    dummy_kernel<<<1, 32>>>();
    prep_kernel<<<1, 128>>>(W_ih);

    xp_kernel<<<(BB * SS) / XROWS, 128>>>(x);
    rec_kernel<<<BB / RBR, RBR * 32>>>(h0, W_hh, b_ih, b_hh, hT);
    stats1_kernel<<<HH, 256>>>(hT);
    fc1_kernel<<<(BB * 16) / 256, 256>>>(hT, bn1g, bn1b, fc1W, fc1b);
    stats2_kernel<<<16, 256>>>();
    fc2_kernel<<<(BB * 8) / 256, 256>>>(bn2g, bn2b, fc2W, fc2b, out);
}